// round 5
// baseline (speedup 1.0000x reference)
#include <cuda_runtime.h>
#include <cstdint>

#define DIM 128
#define NMAX 100000
#define EMAX 1600000
#define SCAN_BLK 1024
#define GW 8    // warps per block in fused kernel
#define MB 8    // nodes per warp-batch in fused kernel

// Scratch (device globals: allocation-free per harness rules)
__device__ int   g_deg_out[NMAX];
__device__ int   g_deg_in[NMAX];
__device__ float g_inv_out[NMAX];
__device__ float g_inv_in[NMAX];
__device__ int   g_row_ptr[NMAX + 1];
__device__ int   g_cursor[NMAX];
__device__ int   g_csr_src[EMAX];
__device__ int   g_blksum[256];
__device__ int   g_blkoff[256];
__device__ int   g_scan_tmp[NMAX];
__device__ float g_hsum[DIM];

// ---------------------------------------------------------------------------
// 1) degree counting, vectorized 4 edges/thread
// ---------------------------------------------------------------------------
__global__ void deg_kernel(const int4* __restrict__ src4, const int4* __restrict__ dst4,
                           const int* __restrict__ src, const int* __restrict__ dst,
                           int n4, int n_edges) {
    int i = blockIdx.x * blockDim.x + threadIdx.x;
    if (i < n4) {
        int4 s = src4[i];
        atomicAdd(&g_deg_out[s.x], 1); atomicAdd(&g_deg_out[s.y], 1);
        atomicAdd(&g_deg_out[s.z], 1); atomicAdd(&g_deg_out[s.w], 1);
        int4 d = dst4[i];
        atomicAdd(&g_deg_in[d.x], 1); atomicAdd(&g_deg_in[d.y], 1);
        atomicAdd(&g_deg_in[d.z], 1); atomicAdd(&g_deg_in[d.w], 1);
    }
    // leftover edges (n_edges % 4) handled by one dedicated thread
    if (blockIdx.x == gridDim.x - 1 && threadIdx.x == blockDim.x - 1) {
        for (int e = n4 * 4; e < n_edges; e++) {
            atomicAdd(&g_deg_out[src[e]], 1);
            atomicAdd(&g_deg_in[dst[e]], 1);
        }
    }
}

// ---------------------------------------------------------------------------
// 2) exclusive scan of deg_in -> row_ptr (3-kernel 2-level scan);
//    norms folded into scan3.
// ---------------------------------------------------------------------------
__global__ void scan1_kernel(int n) {
    __shared__ int sm[SCAN_BLK];
    int i = blockIdx.x * SCAN_BLK + threadIdx.x;
    int v = (i < n) ? g_deg_in[i] : 0;
    sm[threadIdx.x] = v;
    __syncthreads();
#pragma unroll
    for (int off = 1; off < SCAN_BLK; off <<= 1) {
        int t = (threadIdx.x >= off) ? sm[threadIdx.x - off] : 0;
        __syncthreads();
        sm[threadIdx.x] += t;
        __syncthreads();
    }
    if (i < n) g_scan_tmp[i] = sm[threadIdx.x] - v;   // exclusive
    if (threadIdx.x == SCAN_BLK - 1) g_blksum[blockIdx.x] = sm[SCAN_BLK - 1];
}

__global__ void scan2_kernel(int nb) {
    __shared__ int sm[256];
    int t = threadIdx.x;
    int v = (t < nb) ? g_blksum[t] : 0;
    sm[t] = v;
    __syncthreads();
#pragma unroll
    for (int off = 1; off < 256; off <<= 1) {
        int u = (t >= off) ? sm[t - off] : 0;
        __syncthreads();
        sm[t] += u;
        __syncthreads();
    }
    if (t < nb) g_blkoff[t] = sm[t] - v;   // exclusive
}

__global__ void scan3_kernel(int n, int n_edges) {
    int i = blockIdx.x * blockDim.x + threadIdx.x;
    if (i < n) {
        int r = g_scan_tmp[i] + g_blkoff[i / SCAN_BLK];
        g_row_ptr[i] = r;
        g_cursor[i] = r;
        g_inv_out[i] = rsqrtf((float)(g_deg_out[i] + 1));
        g_inv_in[i]  = rsqrtf((float)(g_deg_in[i] + 1));
    }
    if (i == 0) g_row_ptr[n] = n_edges;
}

// ---------------------------------------------------------------------------
// 3) bucket fill: csr_src grouped by dst (4 edges/thread)
// ---------------------------------------------------------------------------
__global__ void fill_kernel(const int4* __restrict__ src4, const int4* __restrict__ dst4,
                            const int* __restrict__ src, const int* __restrict__ dst,
                            int n4, int n_edges) {
    int i = blockIdx.x * blockDim.x + threadIdx.x;
    if (i < n4) {
        int4 s = src4[i];
        int4 d = dst4[i];
        g_csr_src[atomicAdd(&g_cursor[d.x], 1)] = s.x;
        g_csr_src[atomicAdd(&g_cursor[d.y], 1)] = s.y;
        g_csr_src[atomicAdd(&g_cursor[d.z], 1)] = s.z;
        g_csr_src[atomicAdd(&g_cursor[d.w], 1)] = s.w;
    }
    if (blockIdx.x == gridDim.x - 1 && threadIdx.x == blockDim.x - 1) {
        for (int e = n4 * 4; e < n_edges; e++)
            g_csr_src[atomicAdd(&g_cursor[dst[e]], 1)] = src[e];
    }
}

// ---------------------------------------------------------------------------
// 4) FUSED: per warp-batch of MB dst rows:
//      a) aggregate x[d] = (sum_s h[s]*wo[s] + h[d]*wo[d]) * wi[d] -> smem
//      b) GEMV y = relu(x @ W1 + b1) with K-paired f32x2 accumulators,
//         accumulate node-sum into g_hsum.
//    Weights staged once per block as Wp[t2][j] = float4(W1[4t2..4t2+3][j]).
//    Lane owns outputs j = {lane, 32+lane, 64+lane, 96+lane}.
// ---------------------------------------------------------------------------
__global__ __launch_bounds__(256, 2)
void fused_kernel(const float4* __restrict__ h4, const float* __restrict__ W1,
                  const float* __restrict__ b1, int n_nodes) {
    extern __shared__ float4 dyn[];
    float4* Wp   = dyn;          // [32][128] float4 = 64KB
    float4* xbuf = dyn + 4096;   // [GW][MB][32] float4 = 32KB

    for (int idx = threadIdx.x; idx < 4096; idx += blockDim.x) {
        int t2 = idx >> 7, j = idx & 127;
        Wp[idx] = make_float4(W1[(4 * t2 + 0) * 128 + j],
                              W1[(4 * t2 + 1) * 128 + j],
                              W1[(4 * t2 + 2) * 128 + j],
                              W1[(4 * t2 + 3) * 128 + j]);
    }
    __syncthreads();

    int lane = threadIdx.x & 31;
    int w    = threadIdx.x >> 5;
    int warp = blockIdx.x * GW + w;
    int nwarp = gridDim.x * GW;

    float bb[4], s[4];
#pragma unroll
    for (int c = 0; c < 4; c++) {
        bb[c] = b1[c * 32 + lane];
        s[c] = 0.f;
    }

    const ulonglong2* Wp2 = (const ulonglong2*)Wp;
    float4* xw = &xbuf[w * MB * 32];
    const ulonglong2* xb = (const ulonglong2*)xw;

    for (int base = warp * MB; base < n_nodes; base += nwarp * MB) {
        // ---- phase A: aggregate MB rows into xw ----
        for (int m = 0; m < MB; m++) {
            int d = base + m;
            float4 out = make_float4(0.f, 0.f, 0.f, 0.f);
            if (d < n_nodes) {
                float wo = g_inv_out[d];
                float4 hv = __ldg(&h4[(size_t)d * 32 + lane]);
                float4 a0 = make_float4(hv.x * wo, hv.y * wo, hv.z * wo, hv.w * wo);
                float4 a1 = make_float4(0.f, 0.f, 0.f, 0.f);
                float4 a2 = make_float4(0.f, 0.f, 0.f, 0.f);
                float4 a3 = make_float4(0.f, 0.f, 0.f, 0.f);
                int beg = g_row_ptr[d], end = g_row_ptr[d + 1];
                int i = beg;
                for (; i + 4 <= end; i += 4) {
                    int s0 = g_csr_src[i],     s1 = g_csr_src[i + 1];
                    int s2 = g_csr_src[i + 2], s3 = g_csr_src[i + 3];
                    float c0 = g_inv_out[s0], c1 = g_inv_out[s1];
                    float c2 = g_inv_out[s2], c3 = g_inv_out[s3];
                    float4 v0 = __ldg(&h4[(size_t)s0 * 32 + lane]);
                    float4 v1 = __ldg(&h4[(size_t)s1 * 32 + lane]);
                    float4 v2 = __ldg(&h4[(size_t)s2 * 32 + lane]);
                    float4 v3 = __ldg(&h4[(size_t)s3 * 32 + lane]);
                    a0.x = fmaf(v0.x, c0, a0.x); a0.y = fmaf(v0.y, c0, a0.y);
                    a0.z = fmaf(v0.z, c0, a0.z); a0.w = fmaf(v0.w, c0, a0.w);
                    a1.x = fmaf(v1.x, c1, a1.x); a1.y = fmaf(v1.y, c1, a1.y);
                    a1.z = fmaf(v1.z, c1, a1.z); a1.w = fmaf(v1.w, c1, a1.w);
                    a2.x = fmaf(v2.x, c2, a2.x); a2.y = fmaf(v2.y, c2, a2.y);
                    a2.z = fmaf(v2.z, c2, a2.z); a2.w = fmaf(v2.w, c2, a2.w);
                    a3.x = fmaf(v3.x, c3, a3.x); a3.y = fmaf(v3.y, c3, a3.y);
                    a3.z = fmaf(v3.z, c3, a3.z); a3.w = fmaf(v3.w, c3, a3.w);
                }
                for (; i < end; i++) {
                    int s0 = g_csr_src[i];
                    float c0 = g_inv_out[s0];
                    float4 v0 = __ldg(&h4[(size_t)s0 * 32 + lane]);
                    a0.x = fmaf(v0.x, c0, a0.x); a0.y = fmaf(v0.y, c0, a0.y);
                    a0.z = fmaf(v0.z, c0, a0.z); a0.w = fmaf(v0.w, c0, a0.w);
                }
                float wi = g_inv_in[d];
                out.x = (a0.x + a1.x + a2.x + a3.x) * wi;
                out.y = (a0.y + a1.y + a2.y + a3.y) * wi;
                out.z = (a0.z + a1.z + a2.z + a3.z) * wi;
                out.w = (a0.w + a1.w + a2.w + a3.w) * wi;
            }
            xw[m * 32 + lane] = out;
        }
        __syncwarp();

        // ---- phase B: GEMV over the MB staged rows ----
        unsigned long long acc[MB][4];
#pragma unroll
        for (int m = 0; m < MB; m++)
#pragma unroll
            for (int c = 0; c < 4; c++) acc[m][c] = 0ull;

#pragma unroll 2
        for (int t2 = 0; t2 < 32; t2++) {
            ulonglong2 wv[4];
#pragma unroll
            for (int c = 0; c < 4; c++)
                wv[c] = Wp2[t2 * 128 + c * 32 + lane];
#pragma unroll
            for (int m = 0; m < MB; m++) {
                ulonglong2 xm = xb[m * 32 + t2];   // broadcast
#pragma unroll
                for (int c = 0; c < 4; c++) {
                    asm("fma.rn.f32x2 %0, %1, %2, %0;"
                        : "+l"(acc[m][c]) : "l"(wv[c].x), "l"(xm.x));
                    asm("fma.rn.f32x2 %0, %1, %2, %0;"
                        : "+l"(acc[m][c]) : "l"(wv[c].y), "l"(xm.y));
                }
            }
        }

#pragma unroll
        for (int m = 0; m < MB; m++) {
            if (base + m >= n_nodes) break;
#pragma unroll
            for (int c = 0; c < 4; c++) {
                unsigned lo, hi;
                asm("mov.b64 {%0, %1}, %2;" : "=r"(lo), "=r"(hi) : "l"(acc[m][c]));
                float y = __uint_as_float(lo) + __uint_as_float(hi) + bb[c];
                s[c] += fmaxf(y, 0.f);
            }
        }
        __syncwarp();   // xbuf reuse safety
    }

#pragma unroll
    for (int c = 0; c < 4; c++)
        atomicAdd(&g_hsum[c * 32 + lane], s[c]);
}

// ---------------------------------------------------------------------------
// 5) classifier heads: out[0:16] = hg@Wc1+bc1, out[16:32] = hg@Wc2+bc2
// ---------------------------------------------------------------------------
__global__ void head_kernel(const float* __restrict__ Wc1, const float* __restrict__ bc1,
                            const float* __restrict__ Wc2, const float* __restrict__ bc2,
                            float* __restrict__ out, float inv_n) {
    int t = threadIdx.x;
    if (t >= 32) return;
    const float* Wc = (t < 16) ? Wc1 : Wc2;
    const float* bc = (t < 16) ? bc1 : bc2;
    int c = t & 15;
    float acc = 0.f;
#pragma unroll 8
    for (int k = 0; k < DIM; k++) acc += g_hsum[k] * Wc[k * 16 + c];
    out[t] = acc * inv_n + bc[c];
}

// ---------------------------------------------------------------------------
extern "C" void kernel_launch(void* const* d_in, const int* in_sizes, int n_in,
                              void* d_out, int out_size) {
    const float* h   = (const float*)d_in[0];
    const int*   src = (const int*)d_in[1];
    const int*   dst = (const int*)d_in[2];
    const float* W1  = (const float*)d_in[3];
    const float* b1  = (const float*)d_in[4];
    const float* Wc1 = (const float*)d_in[5];
    const float* bc1 = (const float*)d_in[6];
    const float* Wc2 = (const float*)d_in[7];
    const float* bc2 = (const float*)d_in[8];

    int n_nodes = in_sizes[0] / DIM;
    int n_edges = in_sizes[1];
    int n4 = n_edges / 4;

    static bool s_init = false;
    if (!s_init) {
        cudaFuncSetAttribute(fused_kernel,
                             cudaFuncAttributeMaxDynamicSharedMemorySize, 98304);
        s_init = true;
    }

    void *do_p = nullptr, *di_p = nullptr, *hs_p = nullptr;
    cudaGetSymbolAddress(&do_p, g_deg_out);
    cudaGetSymbolAddress(&di_p, g_deg_in);
    cudaGetSymbolAddress(&hs_p, g_hsum);

    cudaMemsetAsync(do_p, 0, (size_t)n_nodes * sizeof(int));
    cudaMemsetAsync(di_p, 0, (size_t)n_nodes * sizeof(int));
    cudaMemsetAsync(hs_p, 0, DIM * sizeof(float));

    deg_kernel<<<(n4 + 255) / 256, 256>>>((const int4*)src, (const int4*)dst,
                                          src, dst, n4, n_edges);

    int nb = (n_nodes + SCAN_BLK - 1) / SCAN_BLK;
    scan1_kernel<<<nb, SCAN_BLK>>>(n_nodes);
    scan2_kernel<<<1, 256>>>(nb);
    scan3_kernel<<<(n_nodes + 255) / 256, 256>>>(n_nodes, n_edges);

    fill_kernel<<<(n4 + 255) / 256, 256>>>((const int4*)src, (const int4*)dst,
                                           src, dst, n4, n_edges);

    fused_kernel<<<296, 256, 98304>>>((const float4*)h, W1, b1, n_nodes);

    head_kernel<<<1, 32>>>(Wc1, bc1, Wc2, bc2, (float*)d_out, 1.0f / (float)n_nodes);
}